// round 2
// baseline (speedup 1.0000x reference)
#include <cuda_runtime.h>

// Problem constants
#define BB 64
#define SS 32
#define FF 768
#define UU 768
#define RR (BB*SS)          // 2048 (b,s) rows
#define NSPLIT 512          // VF
#define LOG2E 1.4426950408889634f

// ---------------- static device scratch (no allocation allowed) ----------------
__device__ float4 g_P [UU*UU];   // unfold params (m, c, w, w*erev), [u][j]
__device__ float4 g_PS[FF*UU];   // sensory params, [f][j]
__device__ float  g_X [RR*FF];   // scaled fused input x = in*iw+ib, [r][f]
__device__ float  g_SN[RR*UU];   // sensory numerator  per (r,j)
__device__ float  g_SD[RR*UU];   // sensory denominator per (r,j)
__device__ float  g_V [2][BB*UU];// double-buffered recurrent state
__device__ float  g_rts[RR];     // UNFOLDS / elapsed(b,s)

__device__ __forceinline__ float ex2f(float x){ float y; asm("ex2.approx.ftz.f32 %0, %1;":"=f"(y):"f"(x)); return y; }
__device__ __forceinline__ float rcpf(float x){ float y; asm("rcp.approx.ftz.f32 %0, %1;":"=f"(y):"f"(x)); return y; }

// ---------------- prep: fold parameters ----------------
__global__ void prep_params(const float* __restrict__ s_sig, const float* __restrict__ s_mu,
                            const float* __restrict__ s_w,   const float* __restrict__ s_erev,
                            const float* __restrict__ r_sig, const float* __restrict__ r_mu,
                            const float* __restrict__ r_w,   const float* __restrict__ r_erev){
    int i = blockIdx.x*blockDim.x + threadIdx.x;
    if (i < UU*UU){
        float sg = r_sig[i], m = r_mu[i], w = r_w[i], e = r_erev[i];
        g_P[i]  = make_float4(-sg*LOG2E, sg*m*LOG2E, w, w*e);
        sg = s_sig[i]; m = s_mu[i]; w = s_w[i]; e = s_erev[i];
        g_PS[i] = make_float4(-sg*LOG2E, sg*m*LOG2E, w, w*e);
    }
}

// ---------------- prep: fused+scaled input, rel-ts, zero state ----------------
__global__ void prep_misc(const float* __restrict__ fv, const float* __restrict__ fi,
                          const float* __restrict__ ts,
                          const float* __restrict__ iw, const float* __restrict__ ib){
    int i = blockIdx.x*blockDim.x + threadIdx.x;
    if (i < RR*FF){
        int r = i / FF, f = i - r*FF;
        float v = (f < NSPLIT) ? fv[r*NSPLIT + f] : fi[r*(FF-NSPLIT) + (f - NSPLIT)];
        g_X[i] = fmaf(v, iw[f], ib[f]);
    }
    if (i < BB*UU) g_V[0][i] = 0.0f;
    if (i < RR){
        int b = i / SS, s = i - b*SS;
        g_rts[i] = 6.0f / (ts[b*(SS+1)+s+1] - ts[b*(SS+1)+s]);
    }
}

// ---------------- sensory synapse pass: all (b,s) in parallel ----------------
// grid (UU/32, RR/8), block 256 = 32 j-lanes x 8 r-groups
__global__ void __launch_bounds__(256) sensory_kernel(){
    int jj = threadIdx.x & 31, rr = threadIdx.x >> 5;
    int j = blockIdx.x*32 + jj;
    int r = blockIdx.y*8  + rr;
    const float* __restrict__ xrow = g_X + r*FF;
    float num = 0.f, den = 0.f;
    #pragma unroll 4
    for (int f = 0; f < FF; f++){
        float4 p = __ldg(&g_PS[f*UU + j]);
        float  x = __ldg(&xrow[f]);            // broadcast within warp
        float  z = fmaf(p.x, x, p.y);          // -sigma*log2e*(x-mu)
        float  e = ex2f(z);
        float  sg= rcpf(1.0f + e);             // sigmoid
        num = fmaf(p.w, sg, num);
        den = fmaf(p.z, sg, den);
    }
    g_SN[r*UU + j] = num;
    g_SD[r*UU + j] = den;
}

// ---------------- one ODE unfold ----------------
// grid (UU/32, BB/4), block 128 = 32 j-lanes x 4 b-groups
__global__ void __launch_bounds__(128) unfold_kernel(
        int s, int pin, int pout, int write_h,
        const float* __restrict__ cm, const float* __restrict__ gleak,
        const float* __restrict__ vleak, const float* __restrict__ ow,
        const float* __restrict__ ob, float* __restrict__ hout){
    int jj = threadIdx.x & 31, bb = threadIdx.x >> 5;
    int j = blockIdx.x*32 + jj;
    int b = blockIdx.y*4  + bb;
    int r = b*SS + s;
    const float* __restrict__ vin = g_V[pin] + b*UU;
    float num = g_SN[r*UU + j];
    float den = g_SD[r*UU + j];
    #pragma unroll 4
    for (int u = 0; u < UU; u++){
        float4 p = __ldg(&g_P[u*UU + j]);
        float vb = __ldg(&vin[u]);             // broadcast within warp
        float  z = fmaf(p.x, vb, p.y);
        float  e = ex2f(z);
        float sg = rcpf(1.0f + e);
        num = fmaf(p.w, sg, num);
        den = fmaf(p.z, sg, den);
    }
    float cmt = __ldg(&cm[j]) * g_rts[r];      // cm / (elapsed/6)
    float gl  = __ldg(&gleak[j]);
    float vold= __ldg(&vin[j]);
    float vnew = (cmt*vold + gl*__ldg(&vleak[j]) + num)
               / (cmt + gl + den + 1e-8f);
    g_V[pout][b*UU + j] = vnew;
    if (write_h)
        hout[r*UU + j] = fmaf(vnew, __ldg(&ow[j]), __ldg(&ob[j]));
}

// ---------------- regressor head: LeakyReLU MLP ----------------
// one block per (b,s) row
__global__ void __launch_bounds__(128) head_kernel(
        const float* __restrict__ hseq,
        const float* __restrict__ W1, const float* __restrict__ b1,
        const float* __restrict__ W2, const float* __restrict__ b2,
        float* __restrict__ pose){
    __shared__ float sh[UU];
    __shared__ float hid[128];
    int r = blockIdx.x;
    int t = threadIdx.x;
    const float* hr = hseq + r*UU;
    for (int u = t; u < UU; u += 128) sh[u] = hr[u];
    __syncthreads();
    float acc = b1[t];
    #pragma unroll 4
    for (int u = 0; u < UU; u++)
        acc = fmaf(sh[u], __ldg(&W1[u*128 + t]), acc);
    acc = acc > 0.0f ? acc : 0.1f*acc;         // LeakyReLU(0.1)
    hid[t] = acc;
    __syncthreads();
    if (t < 6){
        float a = b2[t];
        #pragma unroll 4
        for (int k = 0; k < 128; k++)
            a = fmaf(hid[k], __ldg(&W2[k*6 + t]), a);
        pose[r*6 + t] = a;
    }
}

// ---------------- launch ----------------
extern "C" void kernel_launch(void* const* d_in, const int* in_sizes, int n_in,
                              void* d_out, int out_size){
    const float* fv     = (const float*)d_in[0];
    // d_in[1] fv_alter (unused), d_in[3] dec (unused)
    const float* fi     = (const float*)d_in[2];
    const float* ts     = (const float*)d_in[4];
    const float* iw     = (const float*)d_in[5];
    const float* ib     = (const float*)d_in[6];
    const float* s_mu   = (const float*)d_in[7];
    const float* s_sig  = (const float*)d_in[8];
    const float* s_w    = (const float*)d_in[9];
    const float* s_erev = (const float*)d_in[10];
    const float* r_mu   = (const float*)d_in[11];
    const float* r_sig  = (const float*)d_in[12];
    const float* r_w    = (const float*)d_in[13];
    const float* r_erev = (const float*)d_in[14];
    const float* gleak  = (const float*)d_in[15];
    const float* vleak  = (const float*)d_in[16];
    const float* cm     = (const float*)d_in[17];
    const float* ow     = (const float*)d_in[18];
    const float* ob     = (const float*)d_in[19];
    const float* W1     = (const float*)d_in[20];
    const float* b1     = (const float*)d_in[21];
    const float* W2     = (const float*)d_in[22];
    const float* b2     = (const float*)d_in[23];

    float* pose = (float*)d_out;               // (B,1,S,6) = 12288 floats
    float* hseq = (float*)d_out + BB*SS*6;     // (B,S,U)

    prep_params<<<(UU*UU + 255)/256, 256>>>(s_sig, s_mu, s_w, s_erev,
                                            r_sig, r_mu, r_w, r_erev);
    prep_misc<<<(RR*FF + 255)/256, 256>>>(fv, fi, ts, iw, ib);
    sensory_kernel<<<dim3(UU/32, RR/8), 256>>>();

    int pin = 0;
    for (int s = 0; s < SS; s++){
        for (int k = 0; k < 6; k++){
            int pout = pin ^ 1;
            unfold_kernel<<<dim3(UU/32, BB/4), 128>>>(
                s, pin, pout, (k == 5) ? 1 : 0,
                cm, gleak, vleak, ow, ob, hseq);
            pin = pout;
        }
    }

    head_kernel<<<RR, 128>>>(hseq, W1, b1, W2, b2, pose);
}

// round 3
// speedup vs baseline: 2.7439x; 2.7439x over previous
#include <cuda_runtime.h>

// Problem constants
#define BB 64
#define SS 32
#define FF 768
#define UU 768
#define RR (BB*SS)          // 2048 (b,s) rows
#define NSPLIT 512          // VF
#define LOG2E 1.4426950408889634f

// ---------------- static device scratch (no allocation allowed) ----------------
__device__ float4 g_P [UU*UU];   // unfold params (-sig*log2e, sig*mu*log2e, w, w*erev), [u][j]
__device__ float4 g_PS[FF*UU];   // sensory params, [f][j]
__device__ float  g_X [RR*FF];   // scaled fused input x = in*iw+ib, [r][f]
__device__ float  g_SN[RR*UU];   // sensory numerator  per (r,j)
__device__ float  g_SD[RR*UU];   // sensory denominator per (r,j)
__device__ float  g_V [2][BB*UU];// double-buffered recurrent state
__device__ float  g_rts[RR];     // UNFOLDS / elapsed(b,s)

__device__ __forceinline__ float ex2f(float x){ float y; asm("ex2.approx.ftz.f32 %0, %1;":"=f"(y):"f"(x)); return y; }
__device__ __forceinline__ float rcpf(float x){ float y; asm("rcp.approx.ftz.f32 %0, %1;":"=f"(y):"f"(x)); return y; }

// ---------------- prep: fold parameters ----------------
__global__ void prep_params(const float* __restrict__ s_sig, const float* __restrict__ s_mu,
                            const float* __restrict__ s_w,   const float* __restrict__ s_erev,
                            const float* __restrict__ r_sig, const float* __restrict__ r_mu,
                            const float* __restrict__ r_w,   const float* __restrict__ r_erev){
    int i = blockIdx.x*blockDim.x + threadIdx.x;
    if (i < UU*UU){
        float sg = r_sig[i], m = r_mu[i], w = r_w[i], e = r_erev[i];
        g_P[i]  = make_float4(-sg*LOG2E, sg*m*LOG2E, w, w*e);
        sg = s_sig[i]; m = s_mu[i]; w = s_w[i]; e = s_erev[i];
        g_PS[i] = make_float4(-sg*LOG2E, sg*m*LOG2E, w, w*e);
    }
}

// ---------------- prep: fused+scaled input, rel-ts, zero state ----------------
__global__ void prep_misc(const float* __restrict__ fv, const float* __restrict__ fi,
                          const float* __restrict__ ts,
                          const float* __restrict__ iw, const float* __restrict__ ib){
    int i = blockIdx.x*blockDim.x + threadIdx.x;
    if (i < RR*FF){
        int r = i / FF, f = i - r*FF;
        float v = (f < NSPLIT) ? fv[r*NSPLIT + f] : fi[r*(FF-NSPLIT) + (f - NSPLIT)];
        g_X[i] = fmaf(v, iw[f], ib[f]);
    }
    if (i < BB*UU) g_V[0][i] = 0.0f;
    if (i < RR){
        int b = i / SS, s = i - b*SS;
        g_rts[i] = 6.0f / (ts[b*(SS+1)+s+1] - ts[b*(SS+1)+s]);
    }
}

// ---------------- sensory synapse pass: all (b,s) in parallel ----------------
// grid (UU/32, RR/8), block 256 = 32 j-lanes x 8 r-groups
__global__ void __launch_bounds__(256) sensory_kernel(){
    int jj = threadIdx.x & 31, rr = threadIdx.x >> 5;
    int j = blockIdx.x*32 + jj;
    int r = blockIdx.y*8  + rr;
    const float* __restrict__ xrow = g_X + r*FF;
    float num = 0.f, den = 0.f;
    #pragma unroll 4
    for (int f = 0; f < FF; f++){
        float4 p = __ldg(&g_PS[f*UU + j]);
        float  x = __ldg(&xrow[f]);            // broadcast within warp
        float  z = fmaf(p.x, x, p.y);          // -sigma*log2e*(x-mu)
        float  e = ex2f(z);
        float  sg= rcpf(1.0f + e);             // sigmoid
        num = fmaf(p.w, sg, num);
        den = fmaf(p.z, sg, den);
    }
    g_SN[r*UU + j] = num;
    g_SD[r*UU + j] = den;
}

// ---------------- one ODE unfold (v2: 4-way u-split, smem-staged v) ----------------
// block 512 = 32 j-lanes x 4 b x 4 u-chunks; grid (UU/32, BB/4) = (24, 16)
#define UCHUNK (UU/4)        // 192
__global__ void __launch_bounds__(512) unfold_kernel(
        int s, int pin, int pout, int write_h,
        const float* __restrict__ cm, const float* __restrict__ gleak,
        const float* __restrict__ vleak, const float* __restrict__ ow,
        const float* __restrict__ ob, float* __restrict__ hout){
    __shared__ float  sv[4*UU];        // staged v for 4 batches
    __shared__ float2 sred[4][4][32];  // [us][bb][jj] partial (num,den)

    int tid = threadIdx.x;
    int jj = tid & 31;
    int bb = (tid >> 5) & 3;
    int us = tid >> 7;
    int j  = blockIdx.x*32 + jj;
    int b0 = blockIdx.y*4;

    // stage v[b0..b0+3][:] into smem (coalesced)
    const float* __restrict__ vg = g_V[pin] + b0*UU;
    #pragma unroll
    for (int i = tid; i < 4*UU; i += 512) sv[i] = vg[i];
    __syncthreads();

    const float* __restrict__ vrow = sv + bb*UU;
    float num = 0.f, den = 0.f;
    int ubase = us*UCHUNK;
    #pragma unroll 4
    for (int uu = 0; uu < UCHUNK; uu++){
        int u = ubase + uu;
        float4 p = __ldg(&g_P[u*UU + j]);
        float vb = vrow[u];                    // smem broadcast within warp
        float  z = fmaf(p.x, vb, p.y);
        float  e = ex2f(z);
        float sg = rcpf(1.0f + e);
        num = fmaf(p.w, sg, num);
        den = fmaf(p.z, sg, den);
    }
    sred[us][bb][jj] = make_float2(num, den);
    __syncthreads();

    if (us == 0){
        int b = b0 + bb;
        int r = b*SS + s;
        #pragma unroll
        for (int k = 1; k < 4; k++){
            float2 pr = sred[k][bb][jj];
            num += pr.x; den += pr.y;
        }
        num += g_SN[r*UU + j];
        den += g_SD[r*UU + j];
        float cmt = __ldg(&cm[j]) * g_rts[r];  // cm / (elapsed/6)
        float gl  = __ldg(&gleak[j]);
        float vold= vrow[j];
        float vnew = (cmt*vold + gl*__ldg(&vleak[j]) + num)
                   / (cmt + gl + den + 1e-8f);
        g_V[pout][b*UU + j] = vnew;
        if (write_h)
            hout[r*UU + j] = fmaf(vnew, __ldg(&ow[j]), __ldg(&ob[j]));
    }
}

// ---------------- regressor head: LeakyReLU MLP ----------------
// one block per (b,s) row
__global__ void __launch_bounds__(128) head_kernel(
        const float* __restrict__ hseq,
        const float* __restrict__ W1, const float* __restrict__ b1,
        const float* __restrict__ W2, const float* __restrict__ b2,
        float* __restrict__ pose){
    __shared__ float sh[UU];
    __shared__ float hid[128];
    int r = blockIdx.x;
    int t = threadIdx.x;
    const float* hr = hseq + r*UU;
    for (int u = t; u < UU; u += 128) sh[u] = hr[u];
    __syncthreads();
    float acc = b1[t];
    #pragma unroll 4
    for (int u = 0; u < UU; u++)
        acc = fmaf(sh[u], __ldg(&W1[u*128 + t]), acc);
    acc = acc > 0.0f ? acc : 0.1f*acc;         // LeakyReLU(0.1)
    hid[t] = acc;
    __syncthreads();
    if (t < 6){
        float a = b2[t];
        #pragma unroll 4
        for (int k = 0; k < 128; k++)
            a = fmaf(hid[k], __ldg(&W2[k*6 + t]), a);
        pose[r*6 + t] = a;
    }
}

// ---------------- launch ----------------
extern "C" void kernel_launch(void* const* d_in, const int* in_sizes, int n_in,
                              void* d_out, int out_size){
    const float* fv     = (const float*)d_in[0];
    // d_in[1] fv_alter (unused), d_in[3] dec (unused)
    const float* fi     = (const float*)d_in[2];
    const float* ts     = (const float*)d_in[4];
    const float* iw     = (const float*)d_in[5];
    const float* ib     = (const float*)d_in[6];
    const float* s_mu   = (const float*)d_in[7];
    const float* s_sig  = (const float*)d_in[8];
    const float* s_w    = (const float*)d_in[9];
    const float* s_erev = (const float*)d_in[10];
    const float* r_mu   = (const float*)d_in[11];
    const float* r_sig  = (const float*)d_in[12];
    const float* r_w    = (const float*)d_in[13];
    const float* r_erev = (const float*)d_in[14];
    const float* gleak  = (const float*)d_in[15];
    const float* vleak  = (const float*)d_in[16];
    const float* cm     = (const float*)d_in[17];
    const float* ow     = (const float*)d_in[18];
    const float* ob     = (const float*)d_in[19];
    const float* W1     = (const float*)d_in[20];
    const float* b1     = (const float*)d_in[21];
    const float* W2     = (const float*)d_in[22];
    const float* b2     = (const float*)d_in[23];

    float* pose = (float*)d_out;               // (B,1,S,6) = 12288 floats
    float* hseq = (float*)d_out + BB*SS*6;     // (B,S,U)

    prep_params<<<(UU*UU + 255)/256, 256>>>(s_sig, s_mu, s_w, s_erev,
                                            r_sig, r_mu, r_w, r_erev);
    prep_misc<<<(RR*FF + 255)/256, 256>>>(fv, fi, ts, iw, ib);
    sensory_kernel<<<dim3(UU/32, RR/8), 256>>>();

    int pin = 0;
    for (int s = 0; s < SS; s++){
        for (int k = 0; k < 6; k++){
            int pout = pin ^ 1;
            unfold_kernel<<<dim3(UU/32, BB/4), 512>>>(
                s, pin, pout, (k == 5) ? 1 : 0,
                cm, gleak, vleak, ow, ob, hseq);
            pin = pout;
        }
    }

    head_kernel<<<RR, 128>>>(hseq, W1, b1, W2, b2, pose);
}

// round 4
// speedup vs baseline: 3.1720x; 1.1561x over previous
#include <cuda_runtime.h>

// Problem constants
#define BB 64
#define SS 32
#define FF 768
#define UU 768
#define RR (BB*SS)          // 2048 (b,s) rows
#define NSPLIT 512          // VF
#define LOG2E 1.4426950408889634f

#define BTILE 4             // batches packed per thread (unfold)
#define USPLIT 8            // u-chunks per block
#define UCH (UU/USPLIT)     // 96
#define RTILE 4             // rows packed per thread (sensory)
#define FSPLIT 8
#define FCH (FF/FSPLIT)     // 96

// ---------------- static device scratch (no allocation allowed) ----------------
__device__ float4 g_P [UU*UU];   // unfold params (-sig*log2e, sig*mu*log2e, w, w*erev), [u][j]
__device__ float4 g_PS[FF*UU];   // sensory params, [f][j]
__device__ float  g_X [RR*FF];   // scaled fused input x = in*iw+ib, [r][f]
__device__ float  g_SN[RR*UU];   // sensory numerator  per (r,j)
__device__ float  g_SD[RR*UU];   // sensory denominator per (r,j)
__device__ float  g_V [2][BB*UU];// double-buffered recurrent state
__device__ float  g_rts[RR];     // UNFOLDS / elapsed(b,s)

__device__ __forceinline__ float ex2f(float x){ float y; asm("ex2.approx.ftz.f32 %0, %1;":"=f"(y):"f"(x)); return y; }
__device__ __forceinline__ float rcpf(float x){ float y; asm("rcp.approx.ftz.f32 %0, %1;":"=f"(y):"f"(x)); return y; }

// ---------------- prep: fold parameters ----------------
__global__ void prep_params(const float* __restrict__ s_sig, const float* __restrict__ s_mu,
                            const float* __restrict__ s_w,   const float* __restrict__ s_erev,
                            const float* __restrict__ r_sig, const float* __restrict__ r_mu,
                            const float* __restrict__ r_w,   const float* __restrict__ r_erev){
    int i = blockIdx.x*blockDim.x + threadIdx.x;
    if (i < UU*UU){
        float sg = r_sig[i], m = r_mu[i], w = r_w[i], e = r_erev[i];
        g_P[i]  = make_float4(-sg*LOG2E, sg*m*LOG2E, w, w*e);
        sg = s_sig[i]; m = s_mu[i]; w = s_w[i]; e = s_erev[i];
        g_PS[i] = make_float4(-sg*LOG2E, sg*m*LOG2E, w, w*e);
    }
}

// ---------------- prep: fused+scaled input, rel-ts, zero state ----------------
__global__ void prep_misc(const float* __restrict__ fv, const float* __restrict__ fi,
                          const float* __restrict__ ts,
                          const float* __restrict__ iw, const float* __restrict__ ib){
    int i = blockIdx.x*blockDim.x + threadIdx.x;
    if (i < RR*FF){
        int r = i / FF, f = i - r*FF;
        float v = (f < NSPLIT) ? fv[r*NSPLIT + f] : fi[r*(FF-NSPLIT) + (f - NSPLIT)];
        g_X[i] = fmaf(v, iw[f], ib[f]);
    }
    if (i < BB*UU) g_V[0][i] = 0.0f;
    if (i < RR){
        int b = i / SS, s = i - b*SS;
        g_rts[i] = 6.0f / (ts[b*(SS+1)+s+1] - ts[b*(SS+1)+s]);
    }
}

// ---------------- sensory synapse pass (r-packed registers) ----------------
// block 256 = 32 j-lanes x 8 f-chunks; each thread handles 4 r rows.
// grid (UU/32, RR/RTILE) = (24, 512)
__global__ void __launch_bounds__(256) sensory_kernel(){
    __shared__ float  sx[FF*RTILE];            // x transposed: sx[f*4+rr]
    __shared__ float2 sred[FSPLIT][32][RTILE]; // partials

    int tid = threadIdx.x;
    int jj = tid & 31, fs = tid >> 5;
    int j  = blockIdx.x*32 + jj;
    int r0 = blockIdx.y*RTILE;

    for (int i = tid; i < RTILE*FF; i += 256){
        int rr = i / FF, f = i - rr*FF;
        sx[f*RTILE + rr] = g_X[(r0+rr)*FF + f];
    }
    __syncthreads();

    float n0=0,n1=0,n2=0,n3=0, d0=0,d1=0,d2=0,d3=0;
    int fbase = fs*FCH;
    const float4* __restrict__ sx4 = (const float4*)sx;
    #pragma unroll 4
    for (int ff = 0; ff < FCH; ff++){
        int f = fbase + ff;
        float4 p = __ldg(&g_PS[f*UU + j]);
        float4 x = sx4[f];                     // broadcast LDS.128
        float s0 = rcpf(1.0f + ex2f(fmaf(p.x, x.x, p.y)));
        float s1 = rcpf(1.0f + ex2f(fmaf(p.x, x.y, p.y)));
        float s2 = rcpf(1.0f + ex2f(fmaf(p.x, x.z, p.y)));
        float s3 = rcpf(1.0f + ex2f(fmaf(p.x, x.w, p.y)));
        n0 = fmaf(p.w, s0, n0); d0 = fmaf(p.z, s0, d0);
        n1 = fmaf(p.w, s1, n1); d1 = fmaf(p.z, s1, d1);
        n2 = fmaf(p.w, s2, n2); d2 = fmaf(p.z, s2, d2);
        n3 = fmaf(p.w, s3, n3); d3 = fmaf(p.z, s3, d3);
    }
    sred[fs][jj][0] = make_float2(n0, d0);
    sred[fs][jj][1] = make_float2(n1, d1);
    sred[fs][jj][2] = make_float2(n2, d2);
    sred[fs][jj][3] = make_float2(n3, d3);
    __syncthreads();

    if (fs == 0){
        float nn[RTILE] = {n0,n1,n2,n3};
        float dd[RTILE] = {d0,d1,d2,d3};
        #pragma unroll
        for (int k = 1; k < FSPLIT; k++)
            #pragma unroll
            for (int t = 0; t < RTILE; t++){
                float2 pr = sred[k][jj][t];
                nn[t] += pr.x; dd[t] += pr.y;
            }
        #pragma unroll
        for (int t = 0; t < RTILE; t++){
            g_SN[(r0+t)*UU + j] = nn[t];
            g_SD[(r0+t)*UU + j] = dd[t];
        }
    }
}

// ---------------- one ODE unfold (b-packed registers) ----------------
// block 256 = 32 j-lanes x 8 u-chunks; each thread handles 4 batches.
// grid (UU/32, BB/BTILE) = (24, 16)
__global__ void __launch_bounds__(256) unfold_kernel(
        int s, int pin, int pout, int write_h,
        const float* __restrict__ cm, const float* __restrict__ gleak,
        const float* __restrict__ vleak, const float* __restrict__ ow,
        const float* __restrict__ ob, float* __restrict__ hout){
    __shared__ float  sv[UU*BTILE];            // v transposed: sv[u*4+bb]
    __shared__ float2 sred[USPLIT][32][BTILE];

    int tid = threadIdx.x;
    int jj = tid & 31, us = tid >> 5;
    int j  = blockIdx.x*32 + jj;
    int b0 = blockIdx.y*BTILE;

    const float* __restrict__ vg = g_V[pin] + b0*UU;
    for (int i = tid; i < BTILE*UU; i += 256){
        int bb = i / UU, u = i - bb*UU;
        sv[u*BTILE + bb] = vg[i];
    }
    __syncthreads();

    float n0=0,n1=0,n2=0,n3=0, d0=0,d1=0,d2=0,d3=0;
    int ubase = us*UCH;
    const float4* __restrict__ sv4 = (const float4*)sv;
    #pragma unroll 4
    for (int uu = 0; uu < UCH; uu++){
        int u = ubase + uu;
        float4 p = __ldg(&g_P[u*UU + j]);
        float4 v = sv4[u];                     // broadcast LDS.128
        float s0 = rcpf(1.0f + ex2f(fmaf(p.x, v.x, p.y)));
        float s1 = rcpf(1.0f + ex2f(fmaf(p.x, v.y, p.y)));
        float s2 = rcpf(1.0f + ex2f(fmaf(p.x, v.z, p.y)));
        float s3 = rcpf(1.0f + ex2f(fmaf(p.x, v.w, p.y)));
        n0 = fmaf(p.w, s0, n0); d0 = fmaf(p.z, s0, d0);
        n1 = fmaf(p.w, s1, n1); d1 = fmaf(p.z, s1, d1);
        n2 = fmaf(p.w, s2, n2); d2 = fmaf(p.z, s2, d2);
        n3 = fmaf(p.w, s3, n3); d3 = fmaf(p.z, s3, d3);
    }
    sred[us][jj][0] = make_float2(n0, d0);
    sred[us][jj][1] = make_float2(n1, d1);
    sred[us][jj][2] = make_float2(n2, d2);
    sred[us][jj][3] = make_float2(n3, d3);
    __syncthreads();

    if (us == 0){
        float nn[BTILE] = {n0,n1,n2,n3};
        float dd[BTILE] = {d0,d1,d2,d3};
        #pragma unroll
        for (int k = 1; k < USPLIT; k++)
            #pragma unroll
            for (int t = 0; t < BTILE; t++){
                float2 pr = sred[k][jj][t];
                nn[t] += pr.x; dd[t] += pr.y;
            }
        float cmj = __ldg(&cm[j]);
        float gl  = __ldg(&gleak[j]);
        float glv = gl * __ldg(&vleak[j]);
        float owj = __ldg(&ow[j]);
        float obj = __ldg(&ob[j]);
        #pragma unroll
        for (int t = 0; t < BTILE; t++){
            int b = b0 + t;
            int r = b*SS + s;
            float num = nn[t] + g_SN[r*UU + j];
            float den = dd[t] + g_SD[r*UU + j];
            float cmt = cmj * g_rts[r];
            float vold = sv[j*BTILE + t];
            float vnew = (cmt*vold + glv + num) / (cmt + gl + den + 1e-8f);
            g_V[pout][b*UU + j] = vnew;
            if (write_h)
                hout[r*UU + j] = fmaf(vnew, owj, obj);
        }
    }
}

// ---------------- regressor head: LeakyReLU MLP ----------------
__global__ void __launch_bounds__(128) head_kernel(
        const float* __restrict__ hseq,
        const float* __restrict__ W1, const float* __restrict__ b1,
        const float* __restrict__ W2, const float* __restrict__ b2,
        float* __restrict__ pose){
    __shared__ float sh[UU];
    __shared__ float hid[128];
    int r = blockIdx.x;
    int t = threadIdx.x;
    const float* hr = hseq + r*UU;
    for (int u = t; u < UU; u += 128) sh[u] = hr[u];
    __syncthreads();
    float acc = b1[t];
    #pragma unroll 4
    for (int u = 0; u < UU; u++)
        acc = fmaf(sh[u], __ldg(&W1[u*128 + t]), acc);
    acc = acc > 0.0f ? acc : 0.1f*acc;         // LeakyReLU(0.1)
    hid[t] = acc;
    __syncthreads();
    if (t < 6){
        float a = b2[t];
        #pragma unroll 4
        for (int k = 0; k < 128; k++)
            a = fmaf(hid[k], __ldg(&W2[k*6 + t]), a);
        pose[r*6 + t] = a;
    }
}

// ---------------- launch ----------------
extern "C" void kernel_launch(void* const* d_in, const int* in_sizes, int n_in,
                              void* d_out, int out_size){
    const float* fv     = (const float*)d_in[0];
    // d_in[1] fv_alter (unused), d_in[3] dec (unused)
    const float* fi     = (const float*)d_in[2];
    const float* ts     = (const float*)d_in[4];
    const float* iw     = (const float*)d_in[5];
    const float* ib     = (const float*)d_in[6];
    const float* s_mu   = (const float*)d_in[7];
    const float* s_sig  = (const float*)d_in[8];
    const float* s_w    = (const float*)d_in[9];
    const float* s_erev = (const float*)d_in[10];
    const float* r_mu   = (const float*)d_in[11];
    const float* r_sig  = (const float*)d_in[12];
    const float* r_w    = (const float*)d_in[13];
    const float* r_erev = (const float*)d_in[14];
    const float* gleak  = (const float*)d_in[15];
    const float* vleak  = (const float*)d_in[16];
    const float* cm     = (const float*)d_in[17];
    const float* ow     = (const float*)d_in[18];
    const float* ob     = (const float*)d_in[19];
    const float* W1     = (const float*)d_in[20];
    const float* b1     = (const float*)d_in[21];
    const float* W2     = (const float*)d_in[22];
    const float* b2     = (const float*)d_in[23];

    float* pose = (float*)d_out;               // (B,1,S,6) = 12288 floats
    float* hseq = (float*)d_out + BB*SS*6;     // (B,S,U)

    prep_params<<<(UU*UU + 255)/256, 256>>>(s_sig, s_mu, s_w, s_erev,
                                            r_sig, r_mu, r_w, r_erev);
    prep_misc<<<(RR*FF + 255)/256, 256>>>(fv, fi, ts, iw, ib);
    sensory_kernel<<<dim3(UU/32, RR/RTILE), 256>>>();

    int pin = 0;
    for (int s = 0; s < SS; s++){
        for (int k = 0; k < 6; k++){
            int pout = pin ^ 1;
            unfold_kernel<<<dim3(UU/32, BB/BTILE), 256>>>(
                s, pin, pout, (k == 5) ? 1 : 0,
                cm, gleak, vleak, ow, ob, hseq);
            pin = pout;
        }
    }

    head_kernel<<<RR, 128>>>(hseq, W1, b1, W2, b2, pose);
}

// round 5
// speedup vs baseline: 3.3907x; 1.0689x over previous
#include <cuda_runtime.h>

// Problem constants
#define BB 64
#define SS 32
#define FF 768
#define UU 768
#define RR (BB*SS)          // 2048 (b,s) rows
#define NSPLIT 512          // VF

#define BTILE 8             // batches packed per thread (unfold)
#define USPLIT 16           // u-chunks per block (unfold)
#define UCH (UU/USPLIT)     // 48
#define RTILE 8             // rows packed per thread (sensory)
#define FSPLIT 8
#define FCH (FF/FSPLIT)     // 96

// ---------------- static device scratch (no allocation allowed) ----------------
__device__ float4 g_P [UU*UU];   // unfold params (sig/2, -sig*mu/2, w/2, w*erev/2), [u][j]
__device__ float4 g_PS[FF*UU];   // sensory params, same pack, [f][j]
__device__ float  g_CN[UU];      // per-j constant: sum of w*erev/2 over rec-u AND sensory-f
__device__ float  g_CD[UU];      // per-j constant: sum of w/2       over rec-u AND sensory-f
__device__ float  g_X [RR*FF];   // scaled fused input x = in*iw+ib, [r][f]
__device__ float  g_SN[RR*UU];   // sensory numerator (tanh part + all constants)
__device__ float  g_SD[RR*UU];   // sensory denominator (tanh part + all constants)
__device__ float  g_V [2][BB*UU];// double-buffered recurrent state
__device__ float  g_rts[RR];     // UNFOLDS / elapsed(b,s)

__device__ __forceinline__ float tanhf_fast(float x){
    float y; asm("tanh.approx.f32 %0, %1;":"=f"(y):"f"(x)); return y;
}

// ---------------- prep: fold parameters (tanh form) ----------------
// sigmoid(sig*(x-mu)) = 0.5 + 0.5*tanh( (sig/2)*x - sig*mu/2 )
__global__ void prep_params(const float* __restrict__ s_sig, const float* __restrict__ s_mu,
                            const float* __restrict__ s_w,   const float* __restrict__ s_erev,
                            const float* __restrict__ r_sig, const float* __restrict__ r_mu,
                            const float* __restrict__ r_w,   const float* __restrict__ r_erev){
    int i = blockIdx.x*blockDim.x + threadIdx.x;
    if (i < UU*UU){
        float sg = r_sig[i], m = r_mu[i], w = r_w[i], e = r_erev[i];
        g_P[i]  = make_float4(0.5f*sg, -0.5f*sg*m, 0.5f*w, 0.5f*w*e);
        sg = s_sig[i]; m = s_mu[i]; w = s_w[i]; e = s_erev[i];
        g_PS[i] = make_float4(0.5f*sg, -0.5f*sg*m, 0.5f*w, 0.5f*w*e);
    }
}

// ---------------- prep: per-j constant halves ----------------
__global__ void prep_const(const float* __restrict__ r_w, const float* __restrict__ r_erev,
                           const float* __restrict__ s_w, const float* __restrict__ s_erev){
    int j = blockIdx.x*blockDim.x + threadIdx.x;
    if (j >= UU) return;
    float cn = 0.f, cd = 0.f;
    for (int u = 0; u < UU; u++){
        float w = r_w[u*UU + j], e = r_erev[u*UU + j];
        cn += 0.5f*w*e; cd += 0.5f*w;
    }
    for (int f = 0; f < FF; f++){
        float w = s_w[f*UU + j], e = s_erev[f*UU + j];
        cn += 0.5f*w*e; cd += 0.5f*w;
    }
    g_CN[j] = cn; g_CD[j] = cd;
}

// ---------------- prep: fused+scaled input, rel-ts, zero state ----------------
__global__ void prep_misc(const float* __restrict__ fv, const float* __restrict__ fi,
                          const float* __restrict__ ts,
                          const float* __restrict__ iw, const float* __restrict__ ib){
    int i = blockIdx.x*blockDim.x + threadIdx.x;
    if (i < RR*FF){
        int r = i / FF, f = i - r*FF;
        float v = (f < NSPLIT) ? fv[r*NSPLIT + f] : fi[r*(FF-NSPLIT) + (f - NSPLIT)];
        g_X[i] = fmaf(v, iw[f], ib[f]);
    }
    if (i < BB*UU) g_V[0][i] = 0.0f;
    if (i < RR){
        int b = i / SS, s = i - b*SS;
        g_rts[i] = 6.0f / (ts[b*(SS+1)+s+1] - ts[b*(SS+1)+s]);
    }
}

// ---------------- sensory synapse pass (8 rows per thread, tanh) ----------------
// block 256 = 32 j-lanes x 8 f-chunks; grid (UU/32, RR/RTILE) = (24, 256)
__global__ void __launch_bounds__(256) sensory_kernel(){
    __shared__ float  sx[FF*RTILE];            // x transposed: sx[f*8+rr]
    __shared__ float2 sred[FSPLIT][32][RTILE];

    int tid = threadIdx.x;
    int jj = tid & 31, fs = tid >> 5;
    int j  = blockIdx.x*32 + jj;
    int r0 = blockIdx.y*RTILE;

    for (int i = tid; i < RTILE*FF; i += 256){
        int rr = i / FF, f = i - rr*FF;
        sx[f*RTILE + rr] = g_X[(r0+rr)*FF + f];
    }
    __syncthreads();

    float nn[RTILE], dd[RTILE];
    #pragma unroll
    for (int t = 0; t < RTILE; t++){ nn[t] = 0.f; dd[t] = 0.f; }

    int fbase = fs*FCH;
    const float4* __restrict__ sx4 = (const float4*)sx;
    #pragma unroll 2
    for (int ff = 0; ff < FCH; ff++){
        int f = fbase + ff;
        float4 p  = __ldg(&g_PS[f*UU + j]);
        float4 xa = sx4[2*f], xb = sx4[2*f + 1];   // broadcast LDS.128
        float xv[RTILE] = {xa.x, xa.y, xa.z, xa.w, xb.x, xb.y, xb.z, xb.w};
        #pragma unroll
        for (int t = 0; t < RTILE; t++){
            float th = tanhf_fast(fmaf(p.x, xv[t], p.y));
            nn[t] = fmaf(p.w, th, nn[t]);
            dd[t] = fmaf(p.z, th, dd[t]);
        }
    }
    #pragma unroll
    for (int t = 0; t < RTILE; t++) sred[fs][jj][t] = make_float2(nn[t], dd[t]);
    __syncthreads();

    if (fs == 0){
        #pragma unroll
        for (int k = 1; k < FSPLIT; k++)
            #pragma unroll
            for (int t = 0; t < RTILE; t++){
                float2 pr = sred[k][jj][t];
                nn[t] += pr.x; dd[t] += pr.y;
            }
        float cn = g_CN[j], cd = g_CD[j];
        #pragma unroll
        for (int t = 0; t < RTILE; t++){
            g_SN[(r0+t)*UU + j] = nn[t] + cn;   // sensory tanh + ALL const halves
            g_SD[(r0+t)*UU + j] = dd[t] + cd;
        }
    }
}

// ---------------- one ODE unfold (8 batches per thread, tanh) ----------------
// block 512 = 32 j-lanes x 16 u-chunks; grid (UU/32, BB/BTILE) = (24, 8)
__global__ void __launch_bounds__(512) unfold_kernel(
        int s, int pin, int pout, int write_h,
        const float* __restrict__ cm, const float* __restrict__ gleak,
        const float* __restrict__ vleak, const float* __restrict__ ow,
        const float* __restrict__ ob, float* __restrict__ hout){
    __shared__ float  sv[UU*BTILE];            // v transposed: sv[u*8+bb]
    __shared__ float2 sred[USPLIT][32][BTILE];

    int tid = threadIdx.x;
    int jj = tid & 31, us = tid >> 5;
    int j  = blockIdx.x*32 + jj;
    int b0 = blockIdx.y*BTILE;

    const float* __restrict__ vg = g_V[pin] + b0*UU;
    for (int i = tid; i < BTILE*UU; i += 512){
        int bb = i / UU, u = i - bb*UU;
        sv[u*BTILE + bb] = vg[i];
    }
    __syncthreads();

    float nn[BTILE], dd[BTILE];
    #pragma unroll
    for (int t = 0; t < BTILE; t++){ nn[t] = 0.f; dd[t] = 0.f; }

    int ubase = us*UCH;
    const float4* __restrict__ sv4 = (const float4*)sv;
    #pragma unroll 2
    for (int uu = 0; uu < UCH; uu++){
        int u = ubase + uu;
        float4 p  = __ldg(&g_P[u*UU + j]);
        float4 va = sv4[2*u], vb = sv4[2*u + 1];   // broadcast LDS.128
        float vv[BTILE] = {va.x, va.y, va.z, va.w, vb.x, vb.y, vb.z, vb.w};
        #pragma unroll
        for (int t = 0; t < BTILE; t++){
            float th = tanhf_fast(fmaf(p.x, vv[t], p.y));
            nn[t] = fmaf(p.w, th, nn[t]);
            dd[t] = fmaf(p.z, th, dd[t]);
        }
    }
    #pragma unroll
    for (int t = 0; t < BTILE; t++) sred[us][jj][t] = make_float2(nn[t], dd[t]);
    __syncthreads();

    if (us == 0){
        #pragma unroll
        for (int k = 1; k < USPLIT; k++)
            #pragma unroll
            for (int t = 0; t < BTILE; t++){
                float2 pr = sred[k][jj][t];
                nn[t] += pr.x; dd[t] += pr.y;
            }
        float cmj = __ldg(&cm[j]);
        float gl  = __ldg(&gleak[j]);
        float glv = gl * __ldg(&vleak[j]);
        float owj = __ldg(&ow[j]);
        float obj = __ldg(&ob[j]);
        #pragma unroll
        for (int t = 0; t < BTILE; t++){
            int b = b0 + t;
            int r = b*SS + s;
            float num = nn[t] + g_SN[r*UU + j];    // SN already holds all constants
            float den = dd[t] + g_SD[r*UU + j];
            float cmt = cmj * g_rts[r];
            float vold = sv[j*BTILE + t];
            float vnew = (cmt*vold + glv + num) / (cmt + gl + den + 1e-8f);
            g_V[pout][b*UU + j] = vnew;
            if (write_h)
                hout[r*UU + j] = fmaf(vnew, owj, obj);
        }
    }
}

// ---------------- regressor head: LeakyReLU MLP ----------------
__global__ void __launch_bounds__(128) head_kernel(
        const float* __restrict__ hseq,
        const float* __restrict__ W1, const float* __restrict__ b1,
        const float* __restrict__ W2, const float* __restrict__ b2,
        float* __restrict__ pose){
    __shared__ float sh[UU];
    __shared__ float hid[128];
    int r = blockIdx.x;
    int t = threadIdx.x;
    const float* hr = hseq + r*UU;
    for (int u = t; u < UU; u += 128) sh[u] = hr[u];
    __syncthreads();
    float acc = b1[t];
    #pragma unroll 4
    for (int u = 0; u < UU; u++)
        acc = fmaf(sh[u], __ldg(&W1[u*128 + t]), acc);
    acc = acc > 0.0f ? acc : 0.1f*acc;         // LeakyReLU(0.1)
    hid[t] = acc;
    __syncthreads();
    if (t < 6){
        float a = b2[t];
        #pragma unroll 4
        for (int k = 0; k < 128; k++)
            a = fmaf(hid[k], __ldg(&W2[k*6 + t]), a);
        pose[r*6 + t] = a;
    }
}

// ---------------- launch ----------------
extern "C" void kernel_launch(void* const* d_in, const int* in_sizes, int n_in,
                              void* d_out, int out_size){
    const float* fv     = (const float*)d_in[0];
    // d_in[1] fv_alter (unused), d_in[3] dec (unused)
    const float* fi     = (const float*)d_in[2];
    const float* ts     = (const float*)d_in[4];
    const float* iw     = (const float*)d_in[5];
    const float* ib     = (const float*)d_in[6];
    const float* s_mu   = (const float*)d_in[7];
    const float* s_sig  = (const float*)d_in[8];
    const float* s_w    = (const float*)d_in[9];
    const float* s_erev = (const float*)d_in[10];
    const float* r_mu   = (const float*)d_in[11];
    const float* r_sig  = (const float*)d_in[12];
    const float* r_w    = (const float*)d_in[13];
    const float* r_erev = (const float*)d_in[14];
    const float* gleak  = (const float*)d_in[15];
    const float* vleak  = (const float*)d_in[16];
    const float* cm     = (const float*)d_in[17];
    const float* ow     = (const float*)d_in[18];
    const float* ob     = (const float*)d_in[19];
    const float* W1     = (const float*)d_in[20];
    const float* b1     = (const float*)d_in[21];
    const float* W2     = (const float*)d_in[22];
    const float* b2     = (const float*)d_in[23];

    float* pose = (float*)d_out;               // (B,1,S,6) = 12288 floats
    float* hseq = (float*)d_out + BB*SS*6;     // (B,S,U)

    prep_params<<<(UU*UU + 255)/256, 256>>>(s_sig, s_mu, s_w, s_erev,
                                            r_sig, r_mu, r_w, r_erev);
    prep_const<<<(UU + 255)/256, 256>>>(r_w, r_erev, s_w, s_erev);
    prep_misc<<<(RR*FF + 255)/256, 256>>>(fv, fi, ts, iw, ib);
    sensory_kernel<<<dim3(UU/32, RR/RTILE), 256>>>();

    int pin = 0;
    for (int s = 0; s < SS; s++){
        for (int k = 0; k < 6; k++){
            int pout = pin ^ 1;
            unfold_kernel<<<dim3(UU/32, BB/BTILE), 512>>>(
                s, pin, pout, (k == 5) ? 1 : 0,
                cm, gleak, vleak, ow, ob, hseq);
            pin = pout;
        }
    }

    head_kernel<<<RR, 128>>>(hseq, W1, b1, W2, b2, pose);
}

// round 10
// speedup vs baseline: 3.7979x; 1.1201x over previous
#include <cuda_runtime.h>

// Problem constants
#define BB 64
#define SS 32
#define FF 768
#define UU 768
#define RR (BB*SS)          // 2048 (b,s) rows
#define NSPLIT 512          // VF

#define BTILE 8             // batches per tile (unfold)
#define KSPL  2             // u-halves across blocks
#define UHALF (UU/KSPL)     // 384
#define USPLIT 16           // u-sub-chunks within block
#define UCH (UHALF/USPLIT)  // 24
#define NTILE 192           // 24 j-tiles x 8 b-tiles

#define RTILE 8             // rows packed per thread (sensory)
#define FSPLIT 8
#define FCH (FF/FSPLIT)     // 96

// ---------------- static device scratch (no allocation allowed) ----------------
__device__ float4 g_P [UU*UU];   // unfold params (sig/2, -sig*mu/2, w/2, w*erev/2), [u][j]
__device__ float4 g_PS[FF*UU];   // sensory params, same pack, [f][j]
__device__ float  g_CN[UU];      // per-j const: sum w*erev/2 (rec + sensory)
__device__ float  g_CD[UU];      // per-j const: sum w/2       (rec + sensory)
__device__ float  g_X [RR*FF];   // scaled fused input, [r][f]
__device__ float  g_SN[RR*UU];   // sensory numerator + consts
__device__ float  g_SD[RR*UU];   // sensory denominator + consts
__device__ float  g_V [2][BB*UU];// double-buffered recurrent state
__device__ float  g_rts[RR];     // UNFOLDS / elapsed(b,s)
__device__ float2 g_PT[KSPL][NTILE][256]; // cross-block u-partials
__device__ int    g_cnt[NTILE];  // arrival counters per tile

__device__ __forceinline__ float tanhf_fast(float x){
    float y; asm("tanh.approx.f32 %0, %1;":"=f"(y):"f"(x)); return y;
}
__device__ __forceinline__ float2 ldcg2(const float2* p){
    float2 v; asm("ld.global.cg.v2.f32 {%0,%1}, [%2];"
                  :"=f"(v.x),"=f"(v.y):"l"(p)); return v;
}

// ---------------- prep: fold parameters (tanh form) ----------------
__global__ void prep_params(const float* __restrict__ s_sig, const float* __restrict__ s_mu,
                            const float* __restrict__ s_w,   const float* __restrict__ s_erev,
                            const float* __restrict__ r_sig, const float* __restrict__ r_mu,
                            const float* __restrict__ r_w,   const float* __restrict__ r_erev){
    int i = blockIdx.x*blockDim.x + threadIdx.x;
    if (i < UU*UU){
        float sg = r_sig[i], m = r_mu[i], w = r_w[i], e = r_erev[i];
        g_P[i]  = make_float4(0.5f*sg, -0.5f*sg*m, 0.5f*w, 0.5f*w*e);
        sg = s_sig[i]; m = s_mu[i]; w = s_w[i]; e = s_erev[i];
        g_PS[i] = make_float4(0.5f*sg, -0.5f*sg*m, 0.5f*w, 0.5f*w*e);
    }
}

// ---------------- prep: per-j constant halves ----------------
__global__ void prep_const(const float* __restrict__ r_w, const float* __restrict__ r_erev,
                           const float* __restrict__ s_w, const float* __restrict__ s_erev){
    int j = blockIdx.x*blockDim.x + threadIdx.x;
    if (j >= UU) return;
    float cn = 0.f, cd = 0.f;
    for (int u = 0; u < UU; u++){
        float w = r_w[u*UU + j], e = r_erev[u*UU + j];
        cn += 0.5f*w*e; cd += 0.5f*w;
    }
    for (int f = 0; f < FF; f++){
        float w = s_w[f*UU + j], e = s_erev[f*UU + j];
        cn += 0.5f*w*e; cd += 0.5f*w;
    }
    g_CN[j] = cn; g_CD[j] = cd;
}

// ---------------- prep: fused+scaled input, rel-ts, zero state/counters ----------------
__global__ void prep_misc(const float* __restrict__ fv, const float* __restrict__ fi,
                          const float* __restrict__ ts,
                          const float* __restrict__ iw, const float* __restrict__ ib){
    int i = blockIdx.x*blockDim.x + threadIdx.x;
    if (i < RR*FF){
        int r = i / FF, f = i - r*FF;
        float v = (f < NSPLIT) ? fv[r*NSPLIT + f] : fi[r*(FF-NSPLIT) + (f - NSPLIT)];
        g_X[i] = fmaf(v, iw[f], ib[f]);
    }
    if (i < BB*UU) g_V[0][i] = 0.0f;
    if (i < NTILE) g_cnt[i] = 0;
    if (i < RR){
        int b = i / SS, s = i - b*SS;
        g_rts[i] = 6.0f / (ts[b*(SS+1)+s+1] - ts[b*(SS+1)+s]);
    }
}

// ---------------- sensory synapse pass (8 rows per thread, tanh) ----------------
// block 256 = 32 j-lanes x 8 f-chunks; grid (UU/32, RR/RTILE) = (24, 256)
__global__ void __launch_bounds__(256) sensory_kernel(){
    __shared__ float  sx[FF*RTILE];            // x transposed: sx[f*8+rr]
    __shared__ float2 sred[FSPLIT][32][RTILE];

    int tid = threadIdx.x;
    int jj = tid & 31, fs = tid >> 5;
    int j  = blockIdx.x*32 + jj;
    int r0 = blockIdx.y*RTILE;

    for (int i = tid; i < RTILE*FF; i += 256){
        int rr = i / FF, f = i - rr*FF;
        sx[f*RTILE + rr] = g_X[(r0+rr)*FF + f];
    }
    __syncthreads();

    float nn[RTILE], dd[RTILE];
    #pragma unroll
    for (int t = 0; t < RTILE; t++){ nn[t] = 0.f; dd[t] = 0.f; }

    int fbase = fs*FCH;
    const float4* __restrict__ sx4 = (const float4*)sx;
    #pragma unroll 2
    for (int ff = 0; ff < FCH; ff++){
        int f = fbase + ff;
        float4 p  = __ldg(&g_PS[f*UU + j]);
        float4 xa = sx4[2*f], xb = sx4[2*f + 1];   // broadcast LDS.128
        float xv[RTILE] = {xa.x, xa.y, xa.z, xa.w, xb.x, xb.y, xb.z, xb.w};
        #pragma unroll
        for (int t = 0; t < RTILE; t++){
            float th = tanhf_fast(fmaf(p.x, xv[t], p.y));
            nn[t] = fmaf(p.w, th, nn[t]);
            dd[t] = fmaf(p.z, th, dd[t]);
        }
    }
    #pragma unroll
    for (int t = 0; t < RTILE; t++) sred[fs][jj][t] = make_float2(nn[t], dd[t]);
    __syncthreads();

    if (fs == 0){
        #pragma unroll
        for (int k = 1; k < FSPLIT; k++)
            #pragma unroll
            for (int t = 0; t < RTILE; t++){
                float2 pr = sred[k][jj][t];
                nn[t] += pr.x; dd[t] += pr.y;
            }
        float cn = g_CN[j], cd = g_CD[j];
        #pragma unroll
        for (int t = 0; t < RTILE; t++){
            g_SN[(r0+t)*UU + j] = nn[t] + cn;
            g_SD[(r0+t)*UU + j] = dd[t] + cd;
        }
    }
}

// ---------------- one ODE unfold (u split across 2 blocks, last-block epilogue) ----------------
// grid (24, 8, 2), block 512 = 32 j-lanes x 16 u-sub-chunks
__global__ void __launch_bounds__(512) unfold_kernel(
        int s, int pin, int pout, int write_h,
        const float* __restrict__ cm, const float* __restrict__ gleak,
        const float* __restrict__ vleak, const float* __restrict__ ow,
        const float* __restrict__ ob, float* __restrict__ hout){
    __shared__ float  sv[UHALF*BTILE];         // v-half transposed: sv[u_local*8+bb]
    __shared__ float2 sred[USPLIT][32][BTILE];
    __shared__ int    s_last;

    int tid = threadIdx.x;
    int jj = tid & 31, us = tid >> 5;
    int jt = blockIdx.x, bt = blockIdx.y, kk = blockIdx.z;
    int j  = jt*32 + jj;
    int b0 = bt*BTILE;
    int tile = bt*24 + jt;

    // stage this u-half of v for 8 batches
    const float* __restrict__ vg = &g_V[pin][b0*UU + kk*UHALF];
    for (int i = tid; i < BTILE*UHALF; i += 512){
        int bb = i / UHALF, u = i - bb*UHALF;
        sv[u*BTILE + bb] = vg[bb*UU + u];
    }
    __syncthreads();

    float nn[BTILE], dd[BTILE];
    #pragma unroll
    for (int t = 0; t < BTILE; t++){ nn[t] = 0.f; dd[t] = 0.f; }

    int ubase = kk*UHALF + us*UCH;
    int ulocal0 = us*UCH;
    const float4* __restrict__ sv4 = (const float4*)sv;
    #pragma unroll 2
    for (int uu = 0; uu < UCH; uu++){
        float4 p  = __ldg(&g_P[(ubase + uu)*UU + j]);
        int ul = ulocal0 + uu;
        float4 va = sv4[2*ul], vb = sv4[2*ul + 1];   // broadcast LDS.128
        float vv[BTILE] = {va.x, va.y, va.z, va.w, vb.x, vb.y, vb.z, vb.w};
        #pragma unroll
        for (int t = 0; t < BTILE; t++){
            float th = tanhf_fast(fmaf(p.x, vv[t], p.y));
            nn[t] = fmaf(p.w, th, nn[t]);
            dd[t] = fmaf(p.z, th, dd[t]);
        }
    }
    #pragma unroll
    for (int t = 0; t < BTILE; t++) sred[us][jj][t] = make_float2(nn[t], dd[t]);
    __syncthreads();

    // cross-us reduce with 256 threads; acc stays in registers
    float2 acc = make_float2(0.f, 0.f);
    int t8 = tid >> 5;                // for tid<256: batch idx, lane jj
    if (tid < 256){
        acc = sred[0][jj][t8];
        #pragma unroll
        for (int k2 = 1; k2 < USPLIT; k2++){
            float2 pr = sred[k2][jj][t8];
            acc.x += pr.x; acc.y += pr.y;
        }
        g_PT[kk][tile][tid] = acc;    // disjoint slot per (kk,tile,thread)
    }
    __threadfence();
    __syncthreads();
    if (tid == 0) s_last = (atomicAdd(&g_cnt[tile], 1) == KSPL-1);
    __syncthreads();

    if (s_last && tid < 256){
        float2 other = ldcg2(&g_PT[1-kk][tile][tid]);   // peer half, L2-coherent
        int b = b0 + t8;
        int r = b*SS + s;
        float num = acc.x + other.x + __ldg(&g_SN[r*UU + j]);
        float den = acc.y + other.y + __ldg(&g_SD[r*UU + j]);
        float gl  = __ldg(&gleak[j]);
        float cmt = __ldg(&cm[j]) * g_rts[r];
        float vold = __ldg(&g_V[pin][b*UU + j]);
        float vnew = (cmt*vold + gl*__ldg(&vleak[j]) + num)
                   / (cmt + gl + den + 1e-8f);
        g_V[pout][b*UU + j] = vnew;
        if (write_h)
            hout[r*UU + j] = fmaf(vnew, __ldg(&ow[j]), __ldg(&ob[j]));
    }
    if (s_last && tid == 0) g_cnt[tile] = 0;   // reset for next launch
}

// ---------------- regressor head: LeakyReLU MLP ----------------
__global__ void __launch_bounds__(128) head_kernel(
        const float* __restrict__ hseq,
        const float* __restrict__ W1, const float* __restrict__ b1,
        const float* __restrict__ W2, const float* __restrict__ b2,
        float* __restrict__ pose){
    __shared__ float sh[UU];
    __shared__ float hid[128];
    int r = blockIdx.x;
    int t = threadIdx.x;
    const float* hr = hseq + r*UU;
    for (int u = t; u < UU; u += 128) sh[u] = hr[u];
    __syncthreads();
    float acc = b1[t];
    #pragma unroll 4
    for (int u = 0; u < UU; u++)
        acc = fmaf(sh[u], __ldg(&W1[u*128 + t]), acc);
    acc = acc > 0.0f ? acc : 0.1f*acc;         // LeakyReLU(0.1)
    hid[t] = acc;
    __syncthreads();
    if (t < 6){
        float a = b2[t];
        #pragma unroll 4
        for (int k = 0; k < 128; k++)
            a = fmaf(hid[k], __ldg(&W2[k*6 + t]), a);
        pose[r*6 + t] = a;
    }
}

// ---------------- launch ----------------
extern "C" void kernel_launch(void* const* d_in, const int* in_sizes, int n_in,
                              void* d_out, int out_size){
    const float* fv     = (const float*)d_in[0];
    // d_in[1] fv_alter (unused), d_in[3] dec (unused)
    const float* fi     = (const float*)d_in[2];
    const float* ts     = (const float*)d_in[4];
    const float* iw     = (const float*)d_in[5];
    const float* ib     = (const float*)d_in[6];
    const float* s_mu   = (const float*)d_in[7];
    const float* s_sig  = (const float*)d_in[8];
    const float* s_w    = (const float*)d_in[9];
    const float* s_erev = (const float*)d_in[10];
    const float* r_mu   = (const float*)d_in[11];
    const float* r_sig  = (const float*)d_in[12];
    const float* r_w    = (const float*)d_in[13];
    const float* r_erev = (const float*)d_in[14];
    const float* gleak  = (const float*)d_in[15];
    const float* vleak  = (const float*)d_in[16];
    const float* cm     = (const float*)d_in[17];
    const float* ow     = (const float*)d_in[18];
    const float* ob     = (const float*)d_in[19];
    const float* W1     = (const float*)d_in[20];
    const float* b1     = (const float*)d_in[21];
    const float* W2     = (const float*)d_in[22];
    const float* b2     = (const float*)d_in[23];

    float* pose = (float*)d_out;               // (B,1,S,6) = 12288 floats
    float* hseq = (float*)d_out + BB*SS*6;     // (B,S,U)

    prep_params<<<(UU*UU + 255)/256, 256>>>(s_sig, s_mu, s_w, s_erev,
                                            r_sig, r_mu, r_w, r_erev);
    prep_const<<<(UU + 255)/256, 256>>>(r_w, r_erev, s_w, s_erev);
    prep_misc<<<(RR*FF + 255)/256, 256>>>(fv, fi, ts, iw, ib);
    sensory_kernel<<<dim3(UU/32, RR/RTILE), 256>>>();

    int pin = 0;
    for (int s = 0; s < SS; s++){
        for (int k = 0; k < 6; k++){
            int pout = pin ^ 1;
            unfold_kernel<<<dim3(24, 8, 2), 512>>>(
                s, pin, pout, (k == 5) ? 1 : 0,
                cm, gleak, vleak, ow, ob, hseq);
            pin = pout;
        }
    }

    head_kernel<<<RR, 128>>>(hseq, W1, b1, W2, b2, pose);
}

// round 11
// speedup vs baseline: 5.1540x; 1.3571x over previous
#include <cuda_runtime.h>

// Problem constants
#define BB 64
#define SS 32
#define FF 768
#define UU 768
#define RR (BB*SS)          // 2048 (b,s) rows
#define NSPLIT 512          // VF

// persistent unfold decomposition
#define NBLK 296            // 2 CTAs per SM x 148 SMs, all co-resident
#define NTASK 288           // 12 j-tiles x 8 b-tiles x 3 u-thirds
#define JT 12               // j-tiles of 64
#define BT 8                // b-tiles of 8
#define BTILE 8
#define KSPL 3
#define UTH (UU/KSPL)       // 256
#define NUSUB 8             // u-sub-chunks per block (512 thr = 64 j x 8 us)
#define UCH (UTH/NUSUB)     // 32
#define NTILE (JT*BT)       // 96
#define NROUND (SS*6)       // 192

// sensory decomposition
#define RTILE 8
#define FSPLIT 8
#define FCH (FF/FSPLIT)     // 96

// ---------------- static device scratch (no allocation allowed) ----------------
__device__ float4 g_P [UU*UU];   // unfold params (sig/2, -sig*mu/2, w/2, w*erev/2), [u][j]
__device__ float4 g_PS[FF*UU];   // sensory params, same pack, [f][j]
__device__ float  g_CN[UU];      // per-j const: sum w*erev/2 (rec + sensory)
__device__ float  g_CD[UU];      // per-j const: sum w/2       (rec + sensory)
__device__ float  g_X [RR*FF];   // scaled fused input, [r][f]
__device__ float  g_SN[RR*UU];   // sensory numerator + consts
__device__ float  g_SD[RR*UU];   // sensory denominator + consts
__device__ float  g_V [2][BB*UU];// double-buffered recurrent state
__device__ float  g_rts[RR];     // UNFOLDS / elapsed(b,s)
__device__ float2 g_PT[KSPL][NTILE][512]; // cross-block u-partials
__device__ int    g_cnt[NTILE];  // per-tile monotonic arrival counters
__device__ unsigned g_arrive;    // grid barrier monotonic counter

__device__ __forceinline__ float tanhf_fast(float x){
    float y; asm("tanh.approx.f32 %0, %1;":"=f"(y):"f"(x)); return y;
}
__device__ __forceinline__ float ldcgf(const float* p){
    float v; asm volatile("ld.global.cg.f32 %0, [%1];":"=f"(v):"l"(p)); return v;
}
__device__ __forceinline__ float2 ldcg2(const float2* p){
    float2 v; asm volatile("ld.global.cg.v2.f32 {%0,%1}, [%2];"
                           :"=f"(v.x),"=f"(v.y):"l"(p)); return v;
}
__device__ __forceinline__ unsigned ldcgu(const unsigned* p){
    unsigned v; asm volatile("ld.global.cg.u32 %0, [%1];":"=r"(v):"l"(p)); return v;
}

// ---------------- prep: fold parameters (tanh form) ----------------
// sigmoid(sig*(x-mu)) = 0.5 + 0.5*tanh((sig/2)*x - sig*mu/2)
__global__ void prep_params(const float* __restrict__ s_sig, const float* __restrict__ s_mu,
                            const float* __restrict__ s_w,   const float* __restrict__ s_erev,
                            const float* __restrict__ r_sig, const float* __restrict__ r_mu,
                            const float* __restrict__ r_w,   const float* __restrict__ r_erev){
    int i = blockIdx.x*blockDim.x + threadIdx.x;
    if (i < UU*UU){
        float sg = r_sig[i], m = r_mu[i], w = r_w[i], e = r_erev[i];
        g_P[i]  = make_float4(0.5f*sg, -0.5f*sg*m, 0.5f*w, 0.5f*w*e);
        sg = s_sig[i]; m = s_mu[i]; w = s_w[i]; e = s_erev[i];
        g_PS[i] = make_float4(0.5f*sg, -0.5f*sg*m, 0.5f*w, 0.5f*w*e);
    }
}

// ---------------- prep: per-j constant halves ----------------
__global__ void prep_const(const float* __restrict__ r_w, const float* __restrict__ r_erev,
                           const float* __restrict__ s_w, const float* __restrict__ s_erev){
    int j = blockIdx.x*blockDim.x + threadIdx.x;
    if (j >= UU) return;
    float cn = 0.f, cd = 0.f;
    for (int u = 0; u < UU; u++){
        float w = r_w[u*UU + j], e = r_erev[u*UU + j];
        cn += 0.5f*w*e; cd += 0.5f*w;
    }
    for (int f = 0; f < FF; f++){
        float w = s_w[f*UU + j], e = s_erev[f*UU + j];
        cn += 0.5f*w*e; cd += 0.5f*w;
    }
    g_CN[j] = cn; g_CD[j] = cd;
}

// ---------------- prep: fused+scaled input, rel-ts, zero state/counters ----------------
__global__ void prep_misc(const float* __restrict__ fv, const float* __restrict__ fi,
                          const float* __restrict__ ts,
                          const float* __restrict__ iw, const float* __restrict__ ib){
    int i = blockIdx.x*blockDim.x + threadIdx.x;
    if (i < RR*FF){
        int r = i / FF, f = i - r*FF;
        float v = (f < NSPLIT) ? fv[r*NSPLIT + f] : fi[r*(FF-NSPLIT) + (f - NSPLIT)];
        g_X[i] = fmaf(v, iw[f], ib[f]);
    }
    if (i < BB*UU) g_V[0][i] = 0.0f;
    if (i < NTILE) g_cnt[i] = 0;
    if (i == 0)    g_arrive = 0u;
    if (i < RR){
        int b = i / SS, s = i - b*SS;
        g_rts[i] = 6.0f / (ts[b*(SS+1)+s+1] - ts[b*(SS+1)+s]);
    }
}

// ---------------- sensory synapse pass (8 rows per thread, tanh) ----------------
// block 256 = 32 j-lanes x 8 f-chunks; grid (UU/32, RR/RTILE) = (24, 256)
__global__ void __launch_bounds__(256) sensory_kernel(){
    __shared__ float  sx[FF*RTILE];            // x transposed: sx[f*8+rr]
    __shared__ float2 sred[FSPLIT][32][RTILE];

    int tid = threadIdx.x;
    int jj = tid & 31, fs = tid >> 5;
    int j  = blockIdx.x*32 + jj;
    int r0 = blockIdx.y*RTILE;

    for (int i = tid; i < RTILE*FF; i += 256){
        int rr = i / FF, f = i - rr*FF;
        sx[f*RTILE + rr] = g_X[(r0+rr)*FF + f];
    }
    __syncthreads();

    float nn[RTILE], dd[RTILE];
    #pragma unroll
    for (int t = 0; t < RTILE; t++){ nn[t] = 0.f; dd[t] = 0.f; }

    int fbase = fs*FCH;
    const float4* __restrict__ sx4 = (const float4*)sx;
    #pragma unroll 2
    for (int ff = 0; ff < FCH; ff++){
        int f = fbase + ff;
        float4 p  = __ldg(&g_PS[f*UU + j]);
        float4 xa = sx4[2*f], xb = sx4[2*f + 1];   // broadcast LDS.128
        float xv[RTILE] = {xa.x, xa.y, xa.z, xa.w, xb.x, xb.y, xb.z, xb.w};
        #pragma unroll
        for (int t = 0; t < RTILE; t++){
            float th = tanhf_fast(fmaf(p.x, xv[t], p.y));
            nn[t] = fmaf(p.w, th, nn[t]);
            dd[t] = fmaf(p.z, th, dd[t]);
        }
    }
    #pragma unroll
    for (int t = 0; t < RTILE; t++) sred[fs][jj][t] = make_float2(nn[t], dd[t]);
    __syncthreads();

    if (fs == 0){
        #pragma unroll
        for (int k = 1; k < FSPLIT; k++)
            #pragma unroll
            for (int t = 0; t < RTILE; t++){
                float2 pr = sred[k][jj][t];
                nn[t] += pr.x; dd[t] += pr.y;
            }
        float cn = g_CN[j], cd = g_CD[j];
        #pragma unroll
        for (int t = 0; t < RTILE; t++){
            g_SN[(r0+t)*UU + j] = nn[t] + cn;
            g_SD[(r0+t)*UU + j] = dd[t] + cd;
        }
    }
}

// ---------------- persistent recurrence: all 192 unfolds in one launch ----------------
// grid 296 blocks x 512 thr (2 CTAs/SM, fully co-resident).
// Tasks 0..287: jt = task%12 (64 j), bt = (task/12)%8 (8 b), kk = task/96 (256-u third).
// Cross-k combine via monotonic per-tile counters; grid barrier via monotonic g_arrive.
__global__ void __launch_bounds__(512, 2) recurrence_kernel(
        const float* __restrict__ cm, const float* __restrict__ gleak,
        const float* __restrict__ vleak, const float* __restrict__ ow,
        const float* __restrict__ ob, float* __restrict__ hout){
    __shared__ float  sv[UTH*BTILE];           // v third, transposed: sv[u_local*8+bb]
    __shared__ float2 sred[NUSUB][BTILE][64];  // per-us partials
    __shared__ int    s_last;

    const int tid = threadIdx.x;
    const int bid = blockIdx.x;
    const bool work = (bid < NTASK);
    const int jj = tid & 63;          // j-lane within 64-wide tile
    const int us = tid >> 6;          // u-sub-chunk 0..7
    const int jt = work ? (bid % JT) : 0;
    const int bt = work ? ((bid / JT) % BT) : 0;
    const int kk = work ? (bid / NTILE) : 0;
    const int tile = bt*JT + jt;
    const int j  = jt*64 + jj;
    const int b0 = bt*BTILE;
    const int k1 = (kk+1)%3, k2 = (kk+2)%3;

    // epilogue-role indices: thread o <-> (jo, bo)
    const int jo = tid & 63, bo = tid >> 6;
    const int je = jt*64 + jo;
    const int be = b0 + bo;

    // per-j epilogue constants (loop-invariant)
    const float cmj = __ldg(&cm[je]);
    const float gl  = __ldg(&gleak[je]);
    const float glv = gl * __ldg(&vleak[je]);
    const float owj = __ldg(&ow[je]);
    const float obj = __ldg(&ob[je]);

    for (int r = 0; r < NROUND; r++){
        const int s = r / 6;
        const int pin = r & 1, pout = pin ^ 1;
        const int write_h = ((r % 6) == 5);

        if (work){
            // stage this u-third of v for 8 batches (L2-coherent reads)
            const float* vg = &g_V[pin][b0*UU + kk*UTH];
            #pragma unroll
            for (int i = tid; i < BTILE*UTH; i += 512){
                int bb = i >> 8, u = i & 255;        // UTH=256
                sv[u*BTILE + bb] = ldcgf(&vg[bb*UU + u]);
            }
        }
        __syncthreads();

        if (work){
            float nn[BTILE], dd[BTILE];
            #pragma unroll
            for (int t = 0; t < BTILE; t++){ nn[t] = 0.f; dd[t] = 0.f; }

            const int ubase = kk*UTH + us*UCH;
            const int ul0 = us*UCH;
            const float4* __restrict__ sv4 = (const float4*)sv;
            #pragma unroll 4
            for (int uu = 0; uu < UCH; uu++){
                float4 p  = __ldg(&g_P[(ubase + uu)*UU + j]);
                int ul = ul0 + uu;
                float4 va = sv4[2*ul], vb = sv4[2*ul + 1];   // broadcast LDS.128
                float vv[BTILE] = {va.x, va.y, va.z, va.w, vb.x, vb.y, vb.z, vb.w};
                #pragma unroll
                for (int t = 0; t < BTILE; t++){
                    float th = tanhf_fast(fmaf(p.x, vv[t], p.y));
                    nn[t] = fmaf(p.w, th, nn[t]);
                    dd[t] = fmaf(p.z, th, dd[t]);
                }
            }
            #pragma unroll
            for (int t = 0; t < BTILE; t++) sred[us][t][jj] = make_float2(nn[t], dd[t]);
        }
        __syncthreads();

        float2 acc = make_float2(0.f, 0.f);
        if (work){
            // in-block reduce: thread o owns output (jo, bo)
            #pragma unroll
            for (int k = 0; k < NUSUB; k++){
                float2 pr = sred[k][bo][jo];
                acc.x += pr.x; acc.y += pr.y;
            }
            g_PT[kk][tile][tid] = acc;
            __threadfence();
        }
        __syncthreads();
        if (tid == 0)
            s_last = work ? (atomicAdd(&g_cnt[tile], 1) == r*KSPL + (KSPL-1)) : 0;
        __syncthreads();

        if (work && s_last){
            float2 pa = ldcg2(&g_PT[k1][tile][tid]);
            float2 pb = ldcg2(&g_PT[k2][tile][tid]);
            int rrow = be*SS + s;
            float num = acc.x + pa.x + pb.x + __ldg(&g_SN[rrow*UU + je]);
            float den = acc.y + pa.y + pb.y + __ldg(&g_SD[rrow*UU + je]);
            float cmt = cmj * g_rts[rrow];
            float vold = ldcgf(&g_V[pin][be*UU + je]);
            float vnew = (cmt*vold + glv + num) / (cmt + gl + den + 1e-8f);
            g_V[pout][be*UU + je] = vnew;
            if (write_h)
                hout[rrow*UU + je] = fmaf(vnew, owj, obj);
            __threadfence();
        }
        __syncthreads();

        // grid barrier (monotonic)
        if (tid == 0){
            atomicAdd(&g_arrive, 1u);
            unsigned target = (unsigned)(r + 1) * NBLK;
            while (ldcgu(&g_arrive) < target) __nanosleep(200);
        }
        __syncthreads();
    }
}

// ---------------- regressor head: LeakyReLU MLP ----------------
__global__ void __launch_bounds__(128) head_kernel(
        const float* __restrict__ hseq,
        const float* __restrict__ W1, const float* __restrict__ b1,
        const float* __restrict__ W2, const float* __restrict__ b2,
        float* __restrict__ pose){
    __shared__ float sh[UU];
    __shared__ float hid[128];
    int r = blockIdx.x;
    int t = threadIdx.x;
    const float* hr = hseq + r*UU;
    for (int u = t; u < UU; u += 128) sh[u] = hr[u];
    __syncthreads();
    float acc = b1[t];
    #pragma unroll 4
    for (int u = 0; u < UU; u++)
        acc = fmaf(sh[u], __ldg(&W1[u*128 + t]), acc);
    acc = acc > 0.0f ? acc : 0.1f*acc;         // LeakyReLU(0.1)
    hid[t] = acc;
    __syncthreads();
    if (t < 6){
        float a = b2[t];
        #pragma unroll 4
        for (int k = 0; k < 128; k++)
            a = fmaf(hid[k], __ldg(&W2[k*6 + t]), a);
        pose[r*6 + t] = a;
    }
}

// ---------------- launch ----------------
extern "C" void kernel_launch(void* const* d_in, const int* in_sizes, int n_in,
                              void* d_out, int out_size){
    const float* fv     = (const float*)d_in[0];
    // d_in[1] fv_alter (unused), d_in[3] dec (unused)
    const float* fi     = (const float*)d_in[2];
    const float* ts     = (const float*)d_in[4];
    const float* iw     = (const float*)d_in[5];
    const float* ib     = (const float*)d_in[6];
    const float* s_mu   = (const float*)d_in[7];
    const float* s_sig  = (const float*)d_in[8];
    const float* s_w    = (const float*)d_in[9];
    const float* s_erev = (const float*)d_in[10];
    const float* r_mu   = (const float*)d_in[11];
    const float* r_sig  = (const float*)d_in[12];
    const float* r_w    = (const float*)d_in[13];
    const float* r_erev = (const float*)d_in[14];
    const float* gleak  = (const float*)d_in[15];
    const float* vleak  = (const float*)d_in[16];
    const float* cm     = (const float*)d_in[17];
    const float* ow     = (const float*)d_in[18];
    const float* ob     = (const float*)d_in[19];
    const float* W1     = (const float*)d_in[20];
    const float* b1     = (const float*)d_in[21];
    const float* W2     = (const float*)d_in[22];
    const float* b2     = (const float*)d_in[23];

    float* pose = (float*)d_out;               // (B,1,S,6) = 12288 floats
    float* hseq = (float*)d_out + BB*SS*6;     // (B,S,U)

    prep_params<<<(UU*UU + 255)/256, 256>>>(s_sig, s_mu, s_w, s_erev,
                                            r_sig, r_mu, r_w, r_erev);
    prep_const<<<(UU + 255)/256, 256>>>(r_w, r_erev, s_w, s_erev);
    prep_misc<<<(RR*FF + 255)/256, 256>>>(fv, fi, ts, iw, ib);
    sensory_kernel<<<dim3(UU/32, RR/RTILE), 256>>>();

    recurrence_kernel<<<NBLK, 512>>>(cm, gleak, vleak, ow, ob, hseq);

    head_kernel<<<RR, 128>>>(hseq, W1, b1, W2, b2, pose);
}

// round 15
// speedup vs baseline: 5.3536x; 1.0387x over previous
#include <cuda_runtime.h>

// Problem constants
#define BB 64
#define SS 32
#define FF 768
#define UU 768
#define RR (BB*SS)          // 2048 (b,s) rows
#define NSPLIT 512          // VF

// persistent recurrence: 2 independent groups (b-halves), 148 blocks each
#define NGRP 2
#define GBLK 148            // blocks per group (one per SM)
#define NBLK (NGRP*GBLK)    // 296 total, 2 CTAs/SM co-resident
#define NTASK 144           // tasks per group: 12 jt x 4 bt x 3 kk
#define JT 12               // j-tiles of 64
#define BT 4                // b-tiles of 8 (within the 32-b group half)
#define BTILE 8
#define KSPL 3
#define UTH (UU/KSPL)       // 256
#define NUSUB 8             // u-sub-chunks per block (512 thr = 64 j x 8 us)
#define UCH (UTH/NUSUB)     // 32
#define NTILE (JT*BT)       // 48 tiles per group
#define NROUND (SS*6)       // 192

// sensory decomposition
#define RTILE 8
#define FSPLIT 8
#define FCH (FF/FSPLIT)     // 96

// ---------------- static device scratch (no allocation allowed) ----------------
__device__ float4 g_P [UU*UU];   // unfold params (sig/2, -sig*mu/2, w/2, w*erev/2), [u][j]
__device__ float4 g_PS[FF*UU];   // sensory params, same pack, [f][j]
__device__ float  g_CN[UU];      // per-j const: sum w*erev/2 (rec + sensory)
__device__ float  g_CD[UU];      // per-j const: sum w/2       (rec + sensory)
__device__ float  g_X [RR*FF];   // scaled fused input, [r][f]
__device__ float  g_SN[RR*UU];   // sensory numerator + consts
__device__ float  g_SD[RR*UU];   // sensory denominator + consts
__device__ float  g_V [2][BB*UU];// double-buffered recurrent state
__device__ float  g_rts[RR];     // UNFOLDS / elapsed(b,s)
__device__ float2 g_PT[NGRP][KSPL][NTILE][512]; // cross-block u-partials
__device__ int    g_cnt[NGRP][NTILE];  // per-tile monotonic arrival counters
__device__ unsigned g_arrive[NGRP];    // per-group grid-barrier monotonic counters

__device__ __forceinline__ float tanhf_fast(float x){
    float y; asm("tanh.approx.f32 %0, %1;":"=f"(y):"f"(x)); return y;
}
__device__ __forceinline__ float ldcgf(const float* p){
    float v; asm volatile("ld.global.cg.f32 %0, [%1];":"=f"(v):"l"(p)); return v;
}
__device__ __forceinline__ float2 ldcg2(const float2* p){
    float2 v; asm volatile("ld.global.cg.v2.f32 {%0,%1}, [%2];"
                           :"=f"(v.x),"=f"(v.y):"l"(p)); return v;
}
__device__ __forceinline__ unsigned ldcgu(const unsigned* p){
    unsigned v; asm volatile("ld.global.cg.u32 %0, [%1];":"=r"(v):"l"(p)); return v;
}

// ---------------- prep: fold parameters (tanh form) ----------------
// sigmoid(sig*(x-mu)) = 0.5 + 0.5*tanh((sig/2)*x - sig*mu/2)
__global__ void prep_params(const float* __restrict__ s_sig, const float* __restrict__ s_mu,
                            const float* __restrict__ s_w,   const float* __restrict__ s_erev,
                            const float* __restrict__ r_sig, const float* __restrict__ r_mu,
                            const float* __restrict__ r_w,   const float* __restrict__ r_erev){
    int i = blockIdx.x*blockDim.x + threadIdx.x;
    if (i < UU*UU){
        float sg = r_sig[i], m = r_mu[i], w = r_w[i], e = r_erev[i];
        g_P[i]  = make_float4(0.5f*sg, -0.5f*sg*m, 0.5f*w, 0.5f*w*e);
        sg = s_sig[i]; m = s_mu[i]; w = s_w[i]; e = s_erev[i];
        g_PS[i] = make_float4(0.5f*sg, -0.5f*sg*m, 0.5f*w, 0.5f*w*e);
    }
}

// ---------------- prep: per-j constant halves ----------------
__global__ void prep_const(const float* __restrict__ r_w, const float* __restrict__ r_erev,
                           const float* __restrict__ s_w, const float* __restrict__ s_erev){
    int j = blockIdx.x*blockDim.x + threadIdx.x;
    if (j >= UU) return;
    float cn = 0.f, cd = 0.f;
    for (int u = 0; u < UU; u++){
        float w = r_w[u*UU + j], e = r_erev[u*UU + j];
        cn += 0.5f*w*e; cd += 0.5f*w;
    }
    for (int f = 0; f < FF; f++){
        float w = s_w[f*UU + j], e = s_erev[f*UU + j];
        cn += 0.5f*w*e; cd += 0.5f*w;
    }
    g_CN[j] = cn; g_CD[j] = cd;
}

// ---------------- prep: fused+scaled input, rel-ts, zero state/counters ----------------
__global__ void prep_misc(const float* __restrict__ fv, const float* __restrict__ fi,
                          const float* __restrict__ ts,
                          const float* __restrict__ iw, const float* __restrict__ ib){
    int i = blockIdx.x*blockDim.x + threadIdx.x;
    if (i < RR*FF){
        int r = i / FF, f = i - r*FF;
        float v = (f < NSPLIT) ? fv[r*NSPLIT + f] : fi[r*(FF-NSPLIT) + (f - NSPLIT)];
        g_X[i] = fmaf(v, iw[f], ib[f]);
    }
    if (i < BB*UU) g_V[0][i] = 0.0f;
    if (i < NGRP*NTILE) ((int*)g_cnt)[i] = 0;
    if (i < NGRP) g_arrive[i] = 0u;
    if (i < RR){
        int b = i / SS, s = i - b*SS;
        g_rts[i] = 6.0f / (ts[b*(SS+1)+s+1] - ts[b*(SS+1)+s]);
    }
}

// ---------------- sensory synapse pass (8 rows per thread, tanh) ----------------
// block 256 = 32 j-lanes x 8 f-chunks; grid (UU/32, RR/RTILE) = (24, 256)
__global__ void __launch_bounds__(256) sensory_kernel(){
    __shared__ float  sx[FF*RTILE];            // x transposed: sx[f*8+rr]
    __shared__ float2 sred[FSPLIT][32][RTILE];

    int tid = threadIdx.x;
    int jj = tid & 31, fs = tid >> 5;
    int j  = blockIdx.x*32 + jj;
    int r0 = blockIdx.y*RTILE;

    for (int i = tid; i < RTILE*FF; i += 256){
        int rr = i / FF, f = i - rr*FF;
        sx[f*RTILE + rr] = g_X[(r0+rr)*FF + f];
    }
    __syncthreads();

    float nn[RTILE], dd[RTILE];
    #pragma unroll
    for (int t = 0; t < RTILE; t++){ nn[t] = 0.f; dd[t] = 0.f; }

    int fbase = fs*FCH;
    const float4* __restrict__ sx4 = (const float4*)sx;
    #pragma unroll 2
    for (int ff = 0; ff < FCH; ff++){
        int f = fbase + ff;
        float4 p  = __ldg(&g_PS[f*UU + j]);
        float4 xa = sx4[2*f], xb = sx4[2*f + 1];   // broadcast LDS.128
        float xv[RTILE] = {xa.x, xa.y, xa.z, xa.w, xb.x, xb.y, xb.z, xb.w};
        #pragma unroll
        for (int t = 0; t < RTILE; t++){
            float th = tanhf_fast(fmaf(p.x, xv[t], p.y));
            nn[t] = fmaf(p.w, th, nn[t]);
            dd[t] = fmaf(p.z, th, dd[t]);
        }
    }
    #pragma unroll
    for (int t = 0; t < RTILE; t++) sred[fs][jj][t] = make_float2(nn[t], dd[t]);
    __syncthreads();

    if (fs == 0){
        #pragma unroll
        for (int k = 1; k < FSPLIT; k++)
            #pragma unroll
            for (int t = 0; t < RTILE; t++){
                float2 pr = sred[k][jj][t];
                nn[t] += pr.x; dd[t] += pr.y;
            }
        float cn = g_CN[j], cd = g_CD[j];
        #pragma unroll
        for (int t = 0; t < RTILE; t++){
            g_SN[(r0+t)*UU + j] = nn[t] + cn;
            g_SD[(r0+t)*UU + j] = dd[t] + cd;
        }
    }
}

// ---------------- persistent recurrence: 2 interleaved groups, 192 rounds ----------------
// 296 blocks x 512 thr = 2 CTAs/SM. Group g = bid/148 owns b in [g*32, g*32+32).
// bid and bid+148 map to the same SM -> group A's sync tail hides under group B's compute.
__global__ void __launch_bounds__(512, 2) recurrence_kernel(
        const float* __restrict__ cm, const float* __restrict__ gleak,
        const float* __restrict__ vleak, const float* __restrict__ ow,
        const float* __restrict__ ob, float* __restrict__ hout){
    __shared__ float  sv[UTH*BTILE];           // v third, transposed: sv[u_local*8+bb]
    __shared__ float2 sred[NUSUB][BTILE][64];  // per-us partials
    __shared__ int    s_last;

    const int tid = threadIdx.x;
    const int gid = blockIdx.x / GBLK;         // group 0 or 1
    const int lid = blockIdx.x % GBLK;         // block within group
    const bool work = (lid < NTASK);
    const int jj = tid & 63;                   // j-lane within 64-wide tile
    const int us = tid >> 6;                   // u-sub-chunk 0..7
    const int jt = work ? (lid % JT) : 0;
    const int bt = work ? ((lid / JT) % BT) : 0;
    const int kk = work ? (lid / NTILE) : 0;
    const int tile = bt*JT + jt;
    const int j  = jt*64 + jj;
    const int b0 = gid*32 + bt*BTILE;
    const int k1 = (kk+1)%3, k2 = (kk+2)%3;

    // epilogue-role indices: thread o <-> (jo, bo)
    const int jo = tid & 63, bo = tid >> 6;
    const int je = jt*64 + jo;
    const int be = b0 + bo;

    // per-j epilogue constants (loop-invariant)
    const float cmj = __ldg(&cm[je]);
    const float gl  = __ldg(&gleak[je]);
    const float glv = gl * __ldg(&vleak[je]);
    const float owj = __ldg(&ow[je]);
    const float obj = __ldg(&ob[je]);

    unsigned* const arrive = &g_arrive[gid];

    for (int r = 0; r < NROUND; r++){
        const int s = r / 6;
        const int pin = r & 1, pout = pin ^ 1;
        const int write_h = ((r % 6) == 5);

        if (work){
            // stage this u-third of v for 8 batches (L2-coherent reads)
            const float* vg = &g_V[pin][b0*UU + kk*UTH];
            #pragma unroll
            for (int i = tid; i < BTILE*UTH; i += 512){
                int bb = i >> 8, u = i & 255;        // UTH=256
                sv[u*BTILE + bb] = ldcgf(&vg[bb*UU + u]);
            }
        }
        __syncthreads();

        if (work){
            float nn[BTILE], dd[BTILE];
            #pragma unroll
            for (int t = 0; t < BTILE; t++){ nn[t] = 0.f; dd[t] = 0.f; }

            const int ubase = kk*UTH + us*UCH;
            const int ul0 = us*UCH;
            const float4* __restrict__ sv4 = (const float4*)sv;
            #pragma unroll 4
            for (int uu = 0; uu < UCH; uu++){
                float4 p  = __ldg(&g_P[(ubase + uu)*UU + j]);
                int ul = ul0 + uu;
                float4 va = sv4[2*ul], vb = sv4[2*ul + 1];   // broadcast LDS.128
                float vv[BTILE] = {va.x, va.y, va.z, va.w, vb.x, vb.y, vb.z, vb.w};
                #pragma unroll
                for (int t = 0; t < BTILE; t++){
                    float th = tanhf_fast(fmaf(p.x, vv[t], p.y));
                    nn[t] = fmaf(p.w, th, nn[t]);
                    dd[t] = fmaf(p.z, th, dd[t]);
                }
            }
            #pragma unroll
            for (int t = 0; t < BTILE; t++) sred[us][t][jj] = make_float2(nn[t], dd[t]);
        }
        __syncthreads();

        float2 acc = make_float2(0.f, 0.f);
        if (work){
            // in-block reduce: thread o owns output (jo, bo)
            #pragma unroll
            for (int k = 0; k < NUSUB; k++){
                float2 pr = sred[k][bo][jo];
                acc.x += pr.x; acc.y += pr.y;
            }
            g_PT[gid][kk][tile][tid] = acc;
            __threadfence();
        }
        __syncthreads();
        if (tid == 0)
            s_last = work ? (atomicAdd(&g_cnt[gid][tile], 1) == r*KSPL + (KSPL-1)) : 0;
        __syncthreads();

        if (work && s_last){
            float2 pa = ldcg2(&g_PT[gid][k1][tile][tid]);
            float2 pb = ldcg2(&g_PT[gid][k2][tile][tid]);
            int rrow = be*SS + s;
            float num = acc.x + pa.x + pb.x + __ldg(&g_SN[rrow*UU + je]);
            float den = acc.y + pa.y + pb.y + __ldg(&g_SD[rrow*UU + je]);
            float cmt = cmj * g_rts[rrow];
            float vold = ldcgf(&g_V[pin][be*UU + je]);
            float vnew = (cmt*vold + glv + num) / (cmt + gl + den + 1e-8f);
            g_V[pout][be*UU + je] = vnew;
            if (write_h)
                hout[rrow*UU + je] = fmaf(vnew, owj, obj);
            __threadfence();
        }
        __syncthreads();

        // per-group grid barrier (monotonic)
        if (tid == 0){
            atomicAdd(arrive, 1u);
            unsigned target = (unsigned)(r + 1) * GBLK;
            while (ldcgu(arrive) < target) __nanosleep(100);
        }
        __syncthreads();
    }
}

// ---------------- regressor head: LeakyReLU MLP ----------------
__global__ void __launch_bounds__(128) head_kernel(
        const float* __restrict__ hseq,
        const float* __restrict__ W1, const float* __restrict__ b1,
        const float* __restrict__ W2, const float* __restrict__ b2,
        float* __restrict__ pose){
    __shared__ float sh[UU];
    __shared__ float hid[128];
    int r = blockIdx.x;
    int t = threadIdx.x;
    const float* hr = hseq + r*UU;
    for (int u = t; u < UU; u += 128) sh[u] = hr[u];
    __syncthreads();
    float acc = b1[t];
    #pragma unroll 4
    for (int u = 0; u < UU; u++)
        acc = fmaf(sh[u], __ldg(&W1[u*128 + t]), acc);
    acc = acc > 0.0f ? acc : 0.1f*acc;         // LeakyReLU(0.1)
    hid[t] = acc;
    __syncthreads();
    if (t < 6){
        float a = b2[t];
        #pragma unroll 4
        for (int k = 0; k < 128; k++)
            a = fmaf(hid[k], __ldg(&W2[k*6 + t]), a);
        pose[r*6 + t] = a;
    }
}

// ---------------- launch ----------------
extern "C" void kernel_launch(void* const* d_in, const int* in_sizes, int n_in,
                              void* d_out, int out_size){
    const float* fv     = (const float*)d_in[0];
    // d_in[1] fv_alter (unused), d_in[3] dec (unused)
    const float* fi     = (const float*)d_in[2];
    const float* ts     = (const float*)d_in[4];
    const float* iw     = (const float*)d_in[5];
    const float* ib     = (const float*)d_in[6];
    const float* s_mu   = (const float*)d_in[7];
    const float* s_sig  = (const float*)d_in[8];
    const float* s_w    = (const float*)d_in[9];
    const float* s_erev = (const float*)d_in[10];
    const float* r_mu   = (const float*)d_in[11];
    const float* r_sig  = (const float*)d_in[12];
    const float* r_w    = (const float*)d_in[13];
    const float* r_erev = (const float*)d_in[14];
    const float* gleak  = (const float*)d_in[15];
    const float* vleak  = (const float*)d_in[16];
    const float* cm     = (const float*)d_in[17];
    const float* ow     = (const float*)d_in[18];
    const float* ob     = (const float*)d_in[19];
    const float* W1     = (const float*)d_in[20];
    const float* b1     = (const float*)d_in[21];
    const float* W2     = (const float*)d_in[22];
    const float* b2     = (const float*)d_in[23];

    float* pose = (float*)d_out;               // (B,1,S,6) = 12288 floats
    float* hseq = (float*)d_out + BB*SS*6;     // (B,S,U)

    prep_params<<<(UU*UU + 255)/256, 256>>>(s_sig, s_mu, s_w, s_erev,
                                            r_sig, r_mu, r_w, r_erev);
    prep_const<<<(UU + 255)/256, 256>>>(r_w, r_erev, s_w, s_erev);
    prep_misc<<<(RR*FF + 255)/256, 256>>>(fv, fi, ts, iw, ib);
    sensory_kernel<<<dim3(UU/32, RR/RTILE), 256>>>();

    recurrence_kernel<<<NBLK, 512>>>(cm, gleak, vleak, ow, ob, hseq);

    head_kernel<<<RR, 128>>>(hseq, W1, b1, W2, b2, pose);
}